// round 11
// baseline (speedup 1.0000x reference)
#include <cuda_runtime.h>
#include <cuda_fp16.h>
#include <math.h>
#include <stdint.h>

#define D_MODEL   256
#define N_HEADS   8
#define HEAD_DIM  32
#define N_LEVELS  3
#define N_POINTS  4
#define N_LP      12
#define B_SZ      16
#define LEN_Q     300
#define N_TOTAL   8400
#define NQ        (B_SZ * LEN_Q)      // 4800
#define P_LD      288
#define M1        (B_SZ * N_TOTAL)    // 134400

// Scratch (__device__ globals per allocation-free rule)
__device__ __half   g_valueH [(size_t)M1 * D_MODEL];   // fp16 value
__device__ float    g_params [(size_t)NQ * P_LD];
__device__ float    g_sampled[(size_t)NQ * D_MODEL];
__device__ uint32_t g_BfragH [32768];     // W_val fragment order (N=256)
__device__ uint32_t g_BfragP [36864];     // W_off|W_attn fragment order (N=288)
__device__ uint32_t g_BfragO [32768];     // W_out fragment order (N=256)

// ---------------------------------------------------------------------------
__device__ __forceinline__ uint32_t packh2(float lo, float hi) {
    __half2 h = __floats2half2_rn(lo, hi);
    return *(uint32_t*)&h;
}
__device__ __forceinline__ uint32_t smem_u32(const void* p) {
    uint32_t a;
    asm("{ .reg .u64 t; cvta.to.shared.u64 t, %1; cvt.u32.u64 %0, t; }"
        : "=r"(a) : "l"(p));
    return a;
}
__device__ __forceinline__ void cp_async16(uint32_t dst, const void* src) {
    asm volatile("cp.async.cg.shared.global [%0], [%1], 16;"
                 :: "r"(dst), "l"(src) : "memory");
}
__device__ __forceinline__ void cp_commit() {
    asm volatile("cp.async.commit_group;" ::: "memory");
}
__device__ __forceinline__ void cp_wait0() {
    asm volatile("cp.async.wait_group 0;" ::: "memory");
}
__device__ __forceinline__ void mma_f16(float c[4], uint32_t a0, uint32_t a1,
                                        uint32_t a2, uint32_t a3,
                                        uint32_t b0, uint32_t b1) {
    asm volatile(
        "mma.sync.aligned.m16n8k16.row.col.f32.f16.f16.f32 "
        "{%0,%1,%2,%3}, {%4,%5,%6,%7}, {%8,%9}, {%0,%1,%2,%3};"
        : "+f"(c[0]), "+f"(c[1]), "+f"(c[2]), "+f"(c[3])
        : "r"(a0), "r"(a1), "r"(a2), "r"(a3), "r"(b0), "r"(b1));
}

// ---------------------------------------------------------------------------
// W_val[k][n] -> fp16x2 B-fragment order (N=256 fast path).
// ---------------------------------------------------------------------------
__global__ void prep_w_kernel(const float* __restrict__ W) {
    int id = blockIdx.x * 256 + threadIdx.x;   // 0..32767
    int kc = id >> 12, ci = id & 4095;
    int half = ci & 1, t4v = (ci >> 1) & 3, n = (ci >> 3) & 255, kk16 = ci >> 11;
    int k0 = kc * 32 + kk16 * 16 + half * 8 + t4v * 2;
    g_BfragH[id] = packh2(W[(size_t)k0 * 256 + n], W[(size_t)(k0 + 1) * 256 + n]);
}

// Generic fragment prep for column-concatenated [W1 | W2], K=256.
// id = kc*(Ncols*16) + ((kk16*Ncols + n)*4 + t4)*2 + half
__global__ void prep_small_kernel(const float* __restrict__ W1, int N1,
                                  const float* __restrict__ W2, int N2,
                                  uint32_t* __restrict__ dst,
                                  int Ncols, int total)
{
    int id = blockIdx.x * 256 + threadIdx.x;
    if (id >= total) return;
    int chunkw = Ncols * 16;
    int kc = id / chunkw, ci = id % chunkw;
    int half = ci & 1, t4v = (ci >> 1) & 3;
    int rest = ci >> 3;
    int n = rest % Ncols, kk16 = rest / Ncols;
    int k0 = kc * 32 + kk16 * 16 + half * 8 + t4v * 2;
    float lo, hi;
    if (n < N1) {
        lo = W1[(size_t)k0 * N1 + n];
        hi = W1[(size_t)(k0 + 1) * N1 + n];
    } else {
        lo = W2[(size_t)k0 * N2 + n - N1];
        hi = W2[(size_t)(k0 + 1) * N2 + n - N1];
    }
    dst[id] = packh2(lo, hi);
}

// ---------------------------------------------------------------------------
// GEMM1: value[M1,256] = A[M1,256] @ W_val + bias -> fp16
// CTA 128x256, BK=32, double-buffered, 8 warps, warp tile 64x64.
// ---------------------------------------------------------------------------
#define GEMM1_DYN (48 * 1024)

__global__ __launch_bounds__(256, 1)
void gemm1_mma_kernel(const float* __restrict__ A,
                      const float* __restrict__ bias,
                      __half* __restrict__ C)
{
    extern __shared__ uint32_t smw[];
    uint32_t* sA[2] = { smw,        smw + 2048 };
    uint32_t* sB[2] = { smw + 4096, smw + 8192 };

    const int tid  = threadIdx.x;
    const int warp = tid >> 5;
    const int lane = tid & 31;
    const int g    = lane >> 2;
    const int t4   = lane & 3;
    const int mo   = (warp >> 2) * 4;
    const int no   = (warp & 3) * 64;
    const int bm   = blockIdx.x * 128;

    float acc[4][8][4];
#pragma unroll
    for (int i = 0; i < 4; ++i)
#pragma unroll
        for (int j = 0; j < 8; ++j)
#pragma unroll
            for (int r = 0; r < 4; ++r) acc[i][j][r] = 0.f;

    float4 ra[4];

#define LDA(c)                                                                 \
    do {                                                                       \
        _Pragma("unroll")                                                      \
        for (int i = 0; i < 4; ++i) {                                          \
            int idx = tid + i * 256;                                           \
            int ar = idx >> 3, ac = idx & 7;                                   \
            ra[i] = *(const float4*)(A + (size_t)(bm + ar) * 256 + (c) * 32 + ac * 4); \
        }                                                                      \
    } while (0)

#define STA(s)                                                                 \
    do {                                                                       \
        _Pragma("unroll")                                                      \
        for (int i = 0; i < 4; ++i) {                                          \
            int idx = tid + i * 256;                                           \
            int ar = idx >> 3, ac = idx & 7;                                   \
            int mt = ar >> 4, r = ar & 15;                                     \
            int gl = r & 7, hi = r >> 3;                                       \
            int kk16 = ac >> 2;                                                \
            int half = (ac & 3) >> 1;                                          \
            int t4v0 = (ac & 1) * 2;                                           \
            int base = ((kk16 * 8 + mt) * 32 + gl * 4 + t4v0) * 4 + half * 2 + hi; \
            sA[s][base]     = packh2(ra[i].x, ra[i].y);                        \
            sA[s][base + 4] = packh2(ra[i].z, ra[i].w);                        \
        }                                                                      \
    } while (0)

#define LDB_ASYNC(c, s)                                                        \
    do {                                                                       \
        uint32_t base = smem_u32(sB[s]);                                       \
        const uint32_t* src = g_BfragH + (size_t)(c) * 4096;                   \
        _Pragma("unroll")                                                      \
        for (int i = 0; i < 4; ++i) {                                          \
            int off = (tid + i * 256) * 4;                                     \
            cp_async16(base + off * 4, src + off);                             \
        }                                                                      \
        cp_commit();                                                           \
    } while (0)

    LDA(0);
    LDB_ASYNC(0, 0);
    STA(0);
    cp_wait0();
    __syncthreads();

#pragma unroll 1
    for (int c = 0; c < 8; ++c) {
        const int st = c & 1;
        const bool more = (c < 7);
        if (more) { LDA(c + 1); LDB_ASYNC(c + 1, st ^ 1); }

#pragma unroll
        for (int kk16 = 0; kk16 < 2; ++kk16) {
            uint4 af[4];
#pragma unroll
            for (int i = 0; i < 4; ++i)
                af[i] = *(uint4*)&sA[st][((kk16 * 8 + mo + i) * 32 + lane) * 4];
            uint2 bf[8];
#pragma unroll
            for (int j = 0; j < 8; ++j)
                bf[j] = *(uint2*)&sB[st][((kk16 * 256 + no + 8 * j + g) * 4 + t4) * 2];
#pragma unroll
            for (int i = 0; i < 4; ++i)
#pragma unroll
                for (int j = 0; j < 8; ++j)
                    mma_f16(acc[i][j], af[i].x, af[i].y, af[i].z, af[i].w,
                            bf[j].x, bf[j].y);
        }

        if (more) STA(st ^ 1);
        cp_wait0();
        __syncthreads();
    }

#pragma unroll
    for (int j = 0; j < 8; ++j) {
        int gn = no + 8 * j + 2 * t4;
        float2 bv = *(const float2*)(bias + gn);
#pragma unroll
        for (int i = 0; i < 4; ++i) {
            int gm = bm + (mo + i) * 16 + g;
            *(__half2*)(C + (size_t)gm * 256 + gn) =
                __floats2half2_rn(acc[i][j][0] + bv.x, acc[i][j][1] + bv.y);
            *(__half2*)(C + (size_t)(gm + 8) * 256 + gn) =
                __floats2half2_rn(acc[i][j][2] + bv.x, acc[i][j][3] + bv.y);
        }
    }
#undef LDA
#undef STA
#undef LDB_ASYNC
}

// ---------------------------------------------------------------------------
// Small mma GEMM: C[4800,ldc] = A[4800,256] @ Wfrag + bias (fp16 mma, f32 acc)
// CTA 64 x (32*N8), 4 warps, warp tile 64 x (8*N8). BK=32 double-buffered.
// bias: cols [0,N1) from b1, rest from b2 (N1 % 8 == 0).
// ---------------------------------------------------------------------------
template <int N8>
__global__ __launch_bounds__(128, 4)
void gemm_small_mma(const float* __restrict__ A,
                    const uint32_t* __restrict__ Bfrag, int Ncols,
                    const float* __restrict__ b1, int N1,
                    const float* __restrict__ b2,
                    float* __restrict__ C, int ldc)
{
    constexpr int NTILE = 32 * N8;          // 96 or 128
    constexpr int SBW   = NTILE * 16;       // B stage words
    __shared__ uint32_t smw[2 * 1024 + 2 * SBW];
    uint32_t* sA[2] = { smw,        smw + 1024 };
    uint32_t* sB[2] = { smw + 2048, smw + 2048 + SBW };

    const int tid  = threadIdx.x;
    const int warp = tid >> 5;
    const int lane = tid & 31;
    const int g    = lane >> 2;
    const int t4   = lane & 3;
    const int no   = warp * (8 * N8);
    const int bm   = blockIdx.y * 64;
    const int bn   = blockIdx.x * NTILE;

    float acc[4][N8][4];
#pragma unroll
    for (int i = 0; i < 4; ++i)
#pragma unroll
        for (int j = 0; j < N8; ++j)
#pragma unroll
            for (int r = 0; r < 4; ++r) acc[i][j][r] = 0.f;

    float4 ra[4];

#define LDA_S(c)                                                               \
    do {                                                                       \
        _Pragma("unroll")                                                      \
        for (int i = 0; i < 4; ++i) {                                          \
            int idx = tid + i * 128;                                           \
            int ar = idx >> 3, ac = idx & 7;                                   \
            ra[i] = *(const float4*)(A + (size_t)(bm + ar) * 256 + (c) * 32 + ac * 4); \
        }                                                                      \
    } while (0)

#define STA_S(s)                                                               \
    do {                                                                       \
        _Pragma("unroll")                                                      \
        for (int i = 0; i < 4; ++i) {                                          \
            int idx = tid + i * 128;                                           \
            int ar = idx >> 3, ac = idx & 7;                                   \
            int mt = ar >> 4, r = ar & 15;                                     \
            int gl = r & 7, hi = r >> 3;                                       \
            int kk16 = ac >> 2;                                                \
            int half = (ac & 3) >> 1;                                          \
            int t4v0 = (ac & 1) * 2;                                           \
            int base = ((kk16 * 4 + mt) * 32 + gl * 4 + t4v0) * 4 + half * 2 + hi; \
            sA[s][base]     = packh2(ra[i].x, ra[i].y);                        \
            sA[s][base + 4] = packh2(ra[i].z, ra[i].w);                        \
        }                                                                      \
    } while (0)

#define LDB_S(c, s)                                                            \
    do {                                                                       \
        _Pragma("unroll")                                                      \
        for (int kk = 0; kk < 2; ++kk) {                                       \
            const uint32_t* src = Bfrag + (size_t)(c) * (Ncols * 16)           \
                                  + (kk * Ncols + bn) * 8;                     \
            uint32_t dstb = smem_u32(sB[s]) + kk * (NTILE * 8) * 4;            \
            for (int w = tid * 4; w < NTILE * 8; w += 512)                     \
                cp_async16(dstb + w * 4, src + w);                             \
        }                                                                      \
        cp_commit();                                                           \
    } while (0)

    LDA_S(0);
    LDB_S(0, 0);
    STA_S(0);
    cp_wait0();
    __syncthreads();

#pragma unroll 1
    for (int c = 0; c < 8; ++c) {
        const int st = c & 1;
        const bool more = (c < 7);
        if (more) { LDA_S(c + 1); LDB_S(c + 1, st ^ 1); }

#pragma unroll
        for (int kk16 = 0; kk16 < 2; ++kk16) {
            uint4 af[4];
#pragma unroll
            for (int i = 0; i < 4; ++i)
                af[i] = *(uint4*)&sA[st][((kk16 * 4 + i) * 32 + lane) * 4];
            uint2 bf[N8];
#pragma unroll
            for (int j = 0; j < N8; ++j)
                bf[j] = *(uint2*)&sB[st][((kk16 * NTILE + no + 8 * j + g) * 4 + t4) * 2];
#pragma unroll
            for (int i = 0; i < 4; ++i)
#pragma unroll
                for (int j = 0; j < N8; ++j)
                    mma_f16(acc[i][j], af[i].x, af[i].y, af[i].z, af[i].w,
                            bf[j].x, bf[j].y);
        }

        if (more) STA_S(st ^ 1);
        cp_wait0();
        __syncthreads();
    }

#pragma unroll
    for (int j = 0; j < N8; ++j) {
        int gn = bn + no + 8 * j + 2 * t4;
        float2 bv;
        if (gn < N1) bv = *(const float2*)(b1 + gn);
        else         bv = *(const float2*)(b2 + gn - N1);
#pragma unroll
        for (int i = 0; i < 4; ++i) {
            int gm = bm + i * 16 + g;
            *(float2*)(C + (size_t)gm * ldc + gn) =
                make_float2(acc[i][j][0] + bv.x, acc[i][j][1] + bv.y);
            *(float2*)(C + (size_t)(gm + 8) * ldc + gn) =
                make_float2(acc[i][j][2] + bv.x, acc[i][j][3] + bv.y);
        }
    }
#undef LDA_S
#undef STA_S
#undef LDB_S
}

// ---------------------------------------------------------------------------
// Deformable sampling + softmax, two-phase (round-9 winner).
// ---------------------------------------------------------------------------
__global__ __launch_bounds__(256)
void sample_kernel(const float* __restrict__ ref,
                   float* __restrict__ out)
{
    __shared__ float4 s_w[8][N_LP];
    __shared__ int4   s_o[8][N_LP];

    const int row  = blockIdx.x;
    const int b    = row / LEN_Q;
    const int h    = threadIdx.x >> 5;
    const int lane = threadIdx.x & 31;

    const float* prm  = g_params + row * P_LD;
    const float* attp = prm + 192 + h * N_LP;

    float lgt = (lane < N_LP) ? attp[lane] : -3.0e38f;
    float mx = lgt;
#pragma unroll
    for (int s = 16; s; s >>= 1) mx = fmaxf(mx, __shfl_xor_sync(0xffffffffu, mx, s));
    float e = (lane < N_LP) ? __expf(lgt - mx) : 0.f;
    float sum = e;
#pragma unroll
    for (int s = 16; s; s >>= 1) sum += __shfl_xor_sync(0xffffffffu, sum, s);
    float aw = e / sum;

    if (lane < N_LP) {
        const int   lvl_start[3] = {0, 6400, 8000};
        const int   lvl_W[3]     = {80, 40, 20};
        const float lvl_inv[3]   = {1.f / 80.f, 1.f / 40.f, 1.f / 20.f};
        const int l  = lane >> 2;
        const int Wl = lvl_W[l];
        const int st = lvl_start[l];

        float2 off2 = ((const float2*)(prm + h * (N_LP * 2)))[lane];
        const float* rp = ref + row * (N_LEVELS * 2);
        float lx = fmaf(off2.x, lvl_inv[l], rp[2 * l + 0]);
        float ly = fmaf(off2.y, lvl_inv[l], rp[2 * l + 1]);

        float ix = fmaf(lx, (float)Wl, -0.5f);
        float iy = fmaf(ly, (float)Wl, -0.5f);
        float fix = floorf(ix), fiy = floorf(iy);
        int   x0 = (int)fix,   y0 = (int)fiy;
        float fx = ix - fix,   fy = iy - fiy;
        int   x1 = x0 + 1,     y1 = y0 + 1;

        bool vx0 = (x0 >= 0) & (x0 < Wl);
        bool vx1 = (x1 >= 0) & (x1 < Wl);
        bool vy0 = (y0 >= 0) & (y0 < Wl);
        bool vy1 = (y1 >= 0) & (y1 < Wl);

        int cx0 = min(max(x0, 0), Wl - 1), cx1 = min(max(x1, 0), Wl - 1);
        int cy0 = min(max(y0, 0), Wl - 1), cy1 = min(max(y1, 0), Wl - 1);

        float gx0 = 1.f - fx, gy0 = 1.f - fy;
        float w00 = (vy0 & vx0) ? aw * gy0 * gx0 : 0.f;
        float w01 = (vy0 & vx1) ? aw * gy0 * fx  : 0.f;
        float w10 = (vy1 & vx0) ? aw * fy  * gx0 : 0.f;
        float w11 = (vy1 & vx1) ? aw * fy  * fx  : 0.f;

        int r0 = st + cy0 * Wl, r1 = st + cy1 * Wl;
        s_w[h][lane] = make_float4(w00, w01, w10, w11);
        s_o[h][lane] = make_int4(r0 + cx0, r0 + cx1, r1 + cx0, r1 + cx1);
    }
    __syncwarp();

    const __half* vb = g_valueH + ((unsigned)b * (N_TOTAL * D_MODEL)
                                   + (unsigned)h * HEAD_DIM + (unsigned)lane);
    float acc = 0.f;
#pragma unroll
    for (int j = 0; j < N_LP; ++j) {
        float4 w = s_w[h][j];
        int4   o = s_o[h][j];
        acc = fmaf(w.x, __half2float(vb[(unsigned)o.x << 8]), acc);
        acc = fmaf(w.y, __half2float(vb[(unsigned)o.y << 8]), acc);
        acc = fmaf(w.z, __half2float(vb[(unsigned)o.z << 8]), acc);
        acc = fmaf(w.w, __half2float(vb[(unsigned)o.w << 8]), acc);
    }

    out[row * D_MODEL + h * HEAD_DIM + lane] = acc;
}

// ---------------------------------------------------------------------------
extern "C" void kernel_launch(void* const* d_in, const int* in_sizes, int n_in,
                              void* d_out, int out_size)
{
    const float* query  = (const float*)d_in[0];
    const float* refpts = (const float*)d_in[1];
    const float* inputf = (const float*)d_in[2];
    const float* W_off  = (const float*)d_in[3];
    const float* b_off  = (const float*)d_in[4];
    const float* W_attn = (const float*)d_in[5];
    const float* b_attn = (const float*)d_in[6];
    const float* W_val  = (const float*)d_in[7];
    const float* b_val  = (const float*)d_in[8];
    const float* W_out  = (const float*)d_in[9];
    const float* b_out  = (const float*)d_in[10];
    float* outp = (float*)d_out;

    __half* valueH; cudaGetSymbolAddress((void**)&valueH, g_valueH);
    float* params;  cudaGetSymbolAddress((void**)&params,  g_params);
    float* sampled; cudaGetSymbolAddress((void**)&sampled, g_sampled);
    uint32_t* bfp;  cudaGetSymbolAddress((void**)&bfp,     g_BfragP);
    uint32_t* bfo;  cudaGetSymbolAddress((void**)&bfo,     g_BfragO);

    cudaFuncSetAttribute(gemm1_mma_kernel,
                         cudaFuncAttributeMaxDynamicSharedMemorySize, GEMM1_DYN);

    // 0. weight prepacking (fragment-order fp16)
    prep_w_kernel<<<128, 256>>>(W_val);
    prep_small_kernel<<<144, 256>>>(W_off, 192, W_attn, 96, bfp, 288, 36864);
    prep_small_kernel<<<128, 256>>>(W_out, 256, W_out, 256, bfo, 256, 32768);

    // 1. value projection (mma.sync fp16) -> fp16 value
    gemm1_mma_kernel<<<M1 / 128, 256, GEMM1_DYN>>>(inputf, b_val, valueH);

    // 2. fused offsets+attn: (4800,256)@(256,288)+b -> params (fp16 mma)
    {
        dim3 grid(3, NQ / 64);   // N: 3 x 96, M: 75 x 64
        gemm_small_mma<3><<<grid, 128>>>(query, bfp, 288, b_off, 192, b_attn,
                                         params, P_LD);
    }
    // 3. softmax + deformable bilinear sampling
    sample_kernel<<<NQ, 256>>>(refpts, sampled);

    // 4. output projection: (4800,256)@(256,256)+b -> d_out (fp16 mma)
    {
        dim3 grid(2, NQ / 64);   // N: 2 x 128
        gemm_small_mma<4><<<grid, 128>>>(sampled, bfo, 256, b_out, 256, b_out,
                                         outp, 256);
    }
    (void)in_sizes; (void)n_in; (void)out_size;
}

// round 13
// speedup vs baseline: 1.0230x; 1.0230x over previous
#include <cuda_runtime.h>
#include <cuda_fp16.h>
#include <math.h>
#include <stdint.h>

#define D_MODEL   256
#define N_HEADS   8
#define HEAD_DIM  32
#define N_LEVELS  3
#define N_POINTS  4
#define N_LP      12
#define B_SZ      16
#define LEN_Q     300
#define N_TOTAL   8400
#define NQ        (B_SZ * LEN_Q)      // 4800
#define P_LD      288
#define M1        (B_SZ * N_TOTAL)    // 134400

// Scratch (__device__ globals per allocation-free rule)
__device__ __half   g_valueH [(size_t)M1 * D_MODEL];   // fp16 value
__device__ float    g_params [(size_t)NQ * P_LD];
__device__ float    g_sampled[(size_t)NQ * D_MODEL];
__device__ uint32_t g_BfragH [32768];     // W_val fragment order (N=256)

// ---------------------------------------------------------------------------
__device__ __forceinline__ uint32_t packh2(float lo, float hi) {
    __half2 h = __floats2half2_rn(lo, hi);
    return *(uint32_t*)&h;
}
__device__ __forceinline__ uint32_t smem_u32(const void* p) {
    uint32_t a;
    asm("{ .reg .u64 t; cvta.to.shared.u64 t, %1; cvt.u32.u64 %0, t; }"
        : "=r"(a) : "l"(p));
    return a;
}
__device__ __forceinline__ void cp_async16(uint32_t dst, const void* src) {
    asm volatile("cp.async.cg.shared.global [%0], [%1], 16;"
                 :: "r"(dst), "l"(src) : "memory");
}
__device__ __forceinline__ void cp_commit() {
    asm volatile("cp.async.commit_group;" ::: "memory");
}
__device__ __forceinline__ void cp_wait2() {
    asm volatile("cp.async.wait_group 2;" ::: "memory");
}
__device__ __forceinline__ void mma_f16(float c[4], uint32_t a0, uint32_t a1,
                                        uint32_t a2, uint32_t a3,
                                        uint32_t b0, uint32_t b1) {
    asm volatile(
        "mma.sync.aligned.m16n8k16.row.col.f32.f16.f16.f32 "
        "{%0,%1,%2,%3}, {%4,%5,%6,%7}, {%8,%9}, {%0,%1,%2,%3};"
        : "+f"(c[0]), "+f"(c[1]), "+f"(c[2]), "+f"(c[3])
        : "r"(a0), "r"(a1), "r"(a2), "r"(a3), "r"(b0), "r"(b1));
}

// ---------------------------------------------------------------------------
// W_val[k][n] -> fp16x2 B-fragment order.
// ---------------------------------------------------------------------------
__global__ void prep_w_kernel(const float* __restrict__ W) {
    int id = blockIdx.x * 256 + threadIdx.x;   // 0..32767
    int kc = id >> 12, ci = id & 4095;
    int half = ci & 1, t4v = (ci >> 1) & 3, n = (ci >> 3) & 255, kk16 = ci >> 11;
    int k0 = kc * 32 + kk16 * 16 + half * 8 + t4v * 2;
    g_BfragH[id] = packh2(W[(size_t)k0 * 256 + n], W[(size_t)(k0 + 1) * 256 + n]);
}

// ---------------------------------------------------------------------------
// GEMM1: value[M1,256] = A[M1,256] @ W_val + bias -> fp16
// CTA 128x256, BK=32, 8 warps, warp tile 64x64.
// A: LDG->regs->fragment STS, double-buffered.
// B: 3-stage cp.async pipeline, wait_group 2 (fixes per-chunk latency stall).
// ---------------------------------------------------------------------------
#define GEMM1_DYN (64 * 1024)

__global__ __launch_bounds__(256, 1)
void gemm1_mma_kernel(const float* __restrict__ A,
                      const float* __restrict__ bias,
                      __half* __restrict__ C)
{
    extern __shared__ uint32_t smw[];
    uint32_t* sA[2] = { smw, smw + 2048 };
    uint32_t* sB[3] = { smw + 4096, smw + 8192, smw + 12288 };

    const int tid  = threadIdx.x;
    const int warp = tid >> 5;
    const int lane = tid & 31;
    const int g    = lane >> 2;
    const int t4   = lane & 3;
    const int mo   = (warp >> 2) * 4;
    const int no   = (warp & 3) * 64;
    const int bm   = blockIdx.x * 128;

    float acc[4][8][4];
#pragma unroll
    for (int i = 0; i < 4; ++i)
#pragma unroll
        for (int j = 0; j < 8; ++j)
#pragma unroll
            for (int r = 0; r < 4; ++r) acc[i][j][r] = 0.f;

    float4 ra[4];

#define LDA(c)                                                                 \
    do {                                                                       \
        _Pragma("unroll")                                                      \
        for (int i = 0; i < 4; ++i) {                                          \
            int idx = tid + i * 256;                                           \
            int ar = idx >> 3, ac = idx & 7;                                   \
            ra[i] = *(const float4*)(A + (size_t)(bm + ar) * 256 + (c) * 32 + ac * 4); \
        }                                                                      \
    } while (0)

#define STA(s)                                                                 \
    do {                                                                       \
        _Pragma("unroll")                                                      \
        for (int i = 0; i < 4; ++i) {                                          \
            int idx = tid + i * 256;                                           \
            int ar = idx >> 3, ac = idx & 7;                                   \
            int mt = ar >> 4, r = ar & 15;                                     \
            int gl = r & 7, hi = r >> 3;                                       \
            int kk16 = ac >> 2;                                                \
            int half = (ac & 3) >> 1;                                          \
            int t4v0 = (ac & 1) * 2;                                           \
            int base = ((kk16 * 8 + mt) * 32 + gl * 4 + t4v0) * 4 + half * 2 + hi; \
            sA[s][base]     = packh2(ra[i].x, ra[i].y);                        \
            sA[s][base + 4] = packh2(ra[i].z, ra[i].w);                        \
        }                                                                      \
    } while (0)

#define LDB_ASYNC(c)                                                           \
    do {                                                                       \
        uint32_t base = smem_u32(sB[(c) % 3]);                                 \
        const uint32_t* src = g_BfragH + (size_t)(c) * 4096;                   \
        _Pragma("unroll")                                                      \
        for (int i = 0; i < 4; ++i) {                                          \
            int off = (tid + i * 256) * 4;                                     \
            cp_async16(base + off * 4, src + off);                             \
        }                                                                      \
    } while (0)

    // prologue: B chunks 0 and 1 in flight; A chunk 0 staged
    LDB_ASYNC(0); cp_commit();
    LDB_ASYNC(1); cp_commit();
    LDA(0);
    STA(0);

#pragma unroll 1
    for (int c = 0; c < 8; ++c) {
        const int st = c & 1;
        const bool more = (c < 7);

        if (more) LDA(c + 1);
        if (c + 2 < 8) LDB_ASYNC(c + 2);
        cp_commit();                 // one group per iter (may be empty)
        cp_wait2();                  // B(c) complete; B(c+1),B(c+2) in flight
        __syncthreads();             // B(c) + A(c) visible to all warps

        uint32_t* sBc = sB[c % 3];
#pragma unroll
        for (int kk16 = 0; kk16 < 2; ++kk16) {
            uint4 af[4];
#pragma unroll
            for (int i = 0; i < 4; ++i)
                af[i] = *(uint4*)&sA[st][((kk16 * 8 + mo + i) * 32 + lane) * 4];
            uint2 bf[8];
#pragma unroll
            for (int j = 0; j < 8; ++j)
                bf[j] = *(uint2*)&sBc[((kk16 * 256 + no + 8 * j + g) * 4 + t4) * 2];
#pragma unroll
            for (int i = 0; i < 4; ++i)
#pragma unroll
                for (int j = 0; j < 8; ++j)
                    mma_f16(acc[i][j], af[i].x, af[i].y, af[i].z, af[i].w,
                            bf[j].x, bf[j].y);
        }

        if (more) STA(st ^ 1);
        __syncthreads();             // compute(c) done before stage reuse
    }

#pragma unroll
    for (int j = 0; j < 8; ++j) {
        int gn = no + 8 * j + 2 * t4;
        float2 bv = *(const float2*)(bias + gn);
#pragma unroll
        for (int i = 0; i < 4; ++i) {
            int gm = bm + (mo + i) * 16 + g;
            *(__half2*)(C + (size_t)gm * 256 + gn) =
                __floats2half2_rn(acc[i][j][0] + bv.x, acc[i][j][1] + bv.y);
            *(__half2*)(C + (size_t)(gm + 8) * 256 + gn) =
                __floats2half2_rn(acc[i][j][2] + bv.x, acc[i][j][3] + bv.y);
        }
    }
#undef LDA
#undef STA
#undef LDB_ASYNC
}

// ---------------------------------------------------------------------------
// Small-GEMM kernel (exact fp32), 64x64 tiles, per-thread 4x4, 256 threads.
// Column-concatenated weights: cols [0,N1) from W1/b1, cols [N1,N) from W2/b2.
// ---------------------------------------------------------------------------
__global__ __launch_bounds__(256, 4)
void gemm64_kernel(const float* __restrict__ A,
                   const float* __restrict__ W1, const float* __restrict__ b1,
                   const float* __restrict__ W2, const float* __restrict__ b2,
                   int N1, int N2,
                   float* __restrict__ C,
                   int N, int K, int ldc)
{
    __shared__ float As[16][68];
    __shared__ float Bs[16][68];

    const int bm  = blockIdx.y * 64;
    const int bn  = blockIdx.x * 64;
    const int tid = threadIdx.x;
    const int tx  = tid & 15;
    const int ty  = tid >> 4;

    float acc[4][4];
#pragma unroll
    for (int i = 0; i < 4; ++i)
#pragma unroll
        for (int j = 0; j < 4; ++j) acc[i][j] = 0.f;

    const int a_row = tid >> 2;
    const int a_col = (tid & 3) << 2;
    const int b_row = tid >> 4;
    const int b_col = (tid & 15) << 2;

    for (int k0 = 0; k0 < K; k0 += 16) {
        {
            float4 v = *(const float4*)(A + (size_t)(bm + a_row) * K + k0 + a_col);
            As[a_col + 0][a_row] = v.x;
            As[a_col + 1][a_row] = v.y;
            As[a_col + 2][a_row] = v.z;
            As[a_col + 3][a_row] = v.w;
        }
        {
            int gk = k0 + b_row;
            float v[4];
#pragma unroll
            for (int e = 0; e < 4; ++e) {
                int gn = bn + b_col + e;
                float x = 0.f;
                if (gn < N1)       x = W1[(size_t)gk * N1 + gn];
                else if (gn < N)   x = W2[(size_t)gk * N2 + gn - N1];
                v[e] = x;
            }
            *(float4*)&Bs[b_row][b_col] = make_float4(v[0], v[1], v[2], v[3]);
        }
        __syncthreads();

#pragma unroll
        for (int k = 0; k < 16; ++k) {
            float4 a4 = *(const float4*)&As[k][ty * 4];
            float4 b4 = *(const float4*)&Bs[k][tx * 4];
            float ar2[4] = {a4.x, a4.y, a4.z, a4.w};
            float br2[4] = {b4.x, b4.y, b4.z, b4.w};
#pragma unroll
            for (int i = 0; i < 4; ++i)
#pragma unroll
                for (int j = 0; j < 4; ++j)
                    acc[i][j] += ar2[i] * br2[j];
        }
        __syncthreads();
    }

    float bv[4];
#pragma unroll
    for (int j = 0; j < 4; ++j) {
        int gn = bn + tx * 4 + j;
        bv[j] = (gn < N1) ? b1[gn] : ((gn < N) ? b2[gn - N1] : 0.f);
    }
#pragma unroll
    for (int i = 0; i < 4; ++i) {
        int gm = bm + ty * 4 + i;
#pragma unroll
        for (int j = 0; j < 4; ++j) {
            int gn = bn + tx * 4 + j;
            if (gn < N) C[(size_t)gm * ldc + gn] = acc[i][j] + bv[j];
        }
    }
}

// ---------------------------------------------------------------------------
// Deformable sampling + softmax, two-phase (round-9 winner).
// ---------------------------------------------------------------------------
__global__ __launch_bounds__(256)
void sample_kernel(const float* __restrict__ ref,
                   float* __restrict__ out)
{
    __shared__ float4 s_w[8][N_LP];
    __shared__ int4   s_o[8][N_LP];

    const int row  = blockIdx.x;
    const int b    = row / LEN_Q;
    const int h    = threadIdx.x >> 5;
    const int lane = threadIdx.x & 31;

    const float* prm  = g_params + row * P_LD;
    const float* attp = prm + 192 + h * N_LP;

    float lgt = (lane < N_LP) ? attp[lane] : -3.0e38f;
    float mx = lgt;
#pragma unroll
    for (int s = 16; s; s >>= 1) mx = fmaxf(mx, __shfl_xor_sync(0xffffffffu, mx, s));
    float e = (lane < N_LP) ? __expf(lgt - mx) : 0.f;
    float sum = e;
#pragma unroll
    for (int s = 16; s; s >>= 1) sum += __shfl_xor_sync(0xffffffffu, sum, s);
    float aw = e / sum;

    if (lane < N_LP) {
        const int   lvl_start[3] = {0, 6400, 8000};
        const int   lvl_W[3]     = {80, 40, 20};
        const float lvl_inv[3]   = {1.f / 80.f, 1.f / 40.f, 1.f / 20.f};
        const int l  = lane >> 2;
        const int Wl = lvl_W[l];
        const int st = lvl_start[l];

        float2 off2 = ((const float2*)(prm + h * (N_LP * 2)))[lane];
        const float* rp = ref + row * (N_LEVELS * 2);
        float lx = fmaf(off2.x, lvl_inv[l], rp[2 * l + 0]);
        float ly = fmaf(off2.y, lvl_inv[l], rp[2 * l + 1]);

        float ix = fmaf(lx, (float)Wl, -0.5f);
        float iy = fmaf(ly, (float)Wl, -0.5f);
        float fix = floorf(ix), fiy = floorf(iy);
        int   x0 = (int)fix,   y0 = (int)fiy;
        float fx = ix - fix,   fy = iy - fiy;
        int   x1 = x0 + 1,     y1 = y0 + 1;

        bool vx0 = (x0 >= 0) & (x0 < Wl);
        bool vx1 = (x1 >= 0) & (x1 < Wl);
        bool vy0 = (y0 >= 0) & (y0 < Wl);
        bool vy1 = (y1 >= 0) & (y1 < Wl);

        int cx0 = min(max(x0, 0), Wl - 1), cx1 = min(max(x1, 0), Wl - 1);
        int cy0 = min(max(y0, 0), Wl - 1), cy1 = min(max(y1, 0), Wl - 1);

        float gx0 = 1.f - fx, gy0 = 1.f - fy;
        float w00 = (vy0 & vx0) ? aw * gy0 * gx0 : 0.f;
        float w01 = (vy0 & vx1) ? aw * gy0 * fx  : 0.f;
        float w10 = (vy1 & vx0) ? aw * fy  * gx0 : 0.f;
        float w11 = (vy1 & vx1) ? aw * fy  * fx  : 0.f;

        int r0 = st + cy0 * Wl, r1 = st + cy1 * Wl;
        s_w[h][lane] = make_float4(w00, w01, w10, w11);
        s_o[h][lane] = make_int4(r0 + cx0, r0 + cx1, r1 + cx0, r1 + cx1);
    }
    __syncwarp();

    const __half* vb = g_valueH + ((unsigned)b * (N_TOTAL * D_MODEL)
                                   + (unsigned)h * HEAD_DIM + (unsigned)lane);
    float acc = 0.f;
#pragma unroll
    for (int j = 0; j < N_LP; ++j) {
        float4 w = s_w[h][j];
        int4   o = s_o[h][j];
        acc = fmaf(w.x, __half2float(vb[(unsigned)o.x << 8]), acc);
        acc = fmaf(w.y, __half2float(vb[(unsigned)o.y << 8]), acc);
        acc = fmaf(w.z, __half2float(vb[(unsigned)o.z << 8]), acc);
        acc = fmaf(w.w, __half2float(vb[(unsigned)o.w << 8]), acc);
    }

    out[row * D_MODEL + h * HEAD_DIM + lane] = acc;
}

// ---------------------------------------------------------------------------
extern "C" void kernel_launch(void* const* d_in, const int* in_sizes, int n_in,
                              void* d_out, int out_size)
{
    const float* query  = (const float*)d_in[0];
    const float* refpts = (const float*)d_in[1];
    const float* inputf = (const float*)d_in[2];
    const float* W_off  = (const float*)d_in[3];
    const float* b_off  = (const float*)d_in[4];
    const float* W_attn = (const float*)d_in[5];
    const float* b_attn = (const float*)d_in[6];
    const float* W_val  = (const float*)d_in[7];
    const float* b_val  = (const float*)d_in[8];
    const float* W_out  = (const float*)d_in[9];
    const float* b_out  = (const float*)d_in[10];
    float* outp = (float*)d_out;

    __half* valueH; cudaGetSymbolAddress((void**)&valueH, g_valueH);
    float* params;  cudaGetSymbolAddress((void**)&params,  g_params);
    float* sampled; cudaGetSymbolAddress((void**)&sampled, g_sampled);

    cudaFuncSetAttribute(gemm1_mma_kernel,
                         cudaFuncAttributeMaxDynamicSharedMemorySize, GEMM1_DYN);

    // 0. W_val -> fp16 fragment-order buffer
    prep_w_kernel<<<128, 256>>>(W_val);

    // 1. value projection (mma.sync fp16) -> fp16 value
    gemm1_mma_kernel<<<M1 / 128, 256, GEMM1_DYN>>>(inputf, b_val, valueH);

    // 2. fused offsets+attn: (4800,256)@(256,288)+b -> params (fp32)
    {
        dim3 grid((P_LD + 63) / 64, NQ / 64);
        gemm64_kernel<<<grid, 256>>>(query, W_off, b_off, W_attn, b_attn,
                                     192, 96, params, P_LD, D_MODEL, P_LD);
    }
    // 3. softmax + deformable bilinear sampling
    sample_kernel<<<NQ, 256>>>(refpts, sampled);

    // 4. output projection: (4800,256)@(256,256)+b -> d_out (fp32)
    {
        dim3 grid(256 / 64, NQ / 64);
        gemm64_kernel<<<grid, 256>>>(sampled, W_out, b_out, W_out, b_out,
                                     256, 256, outp, 256, D_MODEL, 256);
    }
    (void)in_sizes; (void)n_in; (void)out_size;
}

// round 16
// speedup vs baseline: 1.2076x; 1.1805x over previous
#include <cuda_runtime.h>
#include <cuda_fp16.h>
#include <math.h>
#include <stdint.h>

#define D_MODEL   256
#define N_HEADS   8
#define HEAD_DIM  32
#define N_LEVELS  3
#define N_POINTS  4
#define N_LP      12
#define B_SZ      16
#define LEN_Q     300
#define N_TOTAL   8400
#define NQ        (B_SZ * LEN_Q)      // 4800
#define P_LD      288
#define M1        (B_SZ * N_TOTAL)    // 134400

// Scratch (allocation-free rule: __device__ globals)
__device__ __half   g_valueH [(size_t)M1 * D_MODEL];   // fp16 value
__device__ float    g_params [(size_t)NQ * P_LD];
__device__ float    g_sampled[(size_t)NQ * D_MODEL];
__device__ uint32_t g_BfragH [32768];     // W_val fragment order (N=256)

// ---------------------------------------------------------------------------
__device__ __forceinline__ uint32_t packh2(float lo, float hi) {
    __half2 h = __floats2half2_rn(lo, hi);
    return *(uint32_t*)&h;
}
__device__ __forceinline__ uint32_t smem_u32(const void* p) {
    uint32_t a;
    asm("{ .reg .u64 t; cvta.to.shared.u64 t, %1; cvt.u32.u64 %0, t; }"
        : "=r"(a) : "l"(p));
    return a;
}
__device__ __forceinline__ void cp_async16(uint32_t dst, const void* src) {
    asm volatile("cp.async.cg.shared.global [%0], [%1], 16;"
                 :: "r"(dst), "l"(src) : "memory");
}
__device__ __forceinline__ void cp_commit() {
    asm volatile("cp.async.commit_group;" ::: "memory");
}
__device__ __forceinline__ void cp_wait0() {
    asm volatile("cp.async.wait_group 0;" ::: "memory");
}
__device__ __forceinline__ void mma_f16(float c[4], uint32_t a0, uint32_t a1,
                                        uint32_t a2, uint32_t a3,
                                        uint32_t b0, uint32_t b1) {
    asm volatile(
        "mma.sync.aligned.m16n8k16.row.col.f32.f16.f16.f32 "
        "{%0,%1,%2,%3}, {%4,%5,%6,%7}, {%8,%9}, {%0,%1,%2,%3};"
        : "+f"(c[0]), "+f"(c[1]), "+f"(c[2]), "+f"(c[3])
        : "r"(a0), "r"(a1), "r"(a2), "r"(a3), "r"(b0), "r"(b1));
}

// ---------------------------------------------------------------------------
// W_val[k][n] -> fp16x2 B-fragment order.
// ---------------------------------------------------------------------------
__global__ void prep_w_kernel(const float* __restrict__ W) {
    int id = blockIdx.x * 256 + threadIdx.x;   // 0..32767
    int kc = id >> 12, ci = id & 4095;
    int half = ci & 1, t4v = (ci >> 1) & 3, n = (ci >> 3) & 255, kk16 = ci >> 11;
    int k0 = kc * 32 + kk16 * 16 + half * 8 + t4v * 2;
    g_BfragH[id] = packh2(W[(size_t)k0 * 256 + n], W[(size_t)(k0 + 1) * 256 + n]);
}

// ---------------------------------------------------------------------------
// GEMM1: value[M1,256] = A[M1,256] @ W_val + bias -> fp16
// CTA 64x256, 128 threads (4 warps), warp tile 64x64, BK=32 double-buffered.
// 2 CTAs/SM -> decoupled barriers keep the HMMA pipe fed.
// smem words: sA 2x1024, sB 2x4096  (40 KB)
// ---------------------------------------------------------------------------
#define GEMM1_DYN (40 * 1024)

__global__ __launch_bounds__(128, 2)
void gemm1_mma_kernel(const float* __restrict__ A,
                      const float* __restrict__ bias,
                      __half* __restrict__ C)
{
    extern __shared__ uint32_t smw[];
    uint32_t* sA[2] = { smw,        smw + 1024 };
    uint32_t* sB[2] = { smw + 2048, smw + 6144 };

    const int tid  = threadIdx.x;
    const int warp = tid >> 5;
    const int lane = tid & 31;
    const int g    = lane >> 2;
    const int t4   = lane & 3;
    const int no   = warp * 64;          // n base (4 warps x 64 = 256)
    const int bm   = blockIdx.x * 64;

    float acc[4][8][4];
#pragma unroll
    for (int i = 0; i < 4; ++i)
#pragma unroll
        for (int j = 0; j < 8; ++j)
#pragma unroll
            for (int r = 0; r < 4; ++r) acc[i][j][r] = 0.f;

    float4 ra[4];

#define LDA(c)                                                                 \
    do {                                                                       \
        _Pragma("unroll")                                                      \
        for (int i = 0; i < 4; ++i) {                                          \
            int idx = tid + i * 128;          /* 0..511 */                     \
            int ar = idx >> 3, ac = idx & 7;  /* row 0..63, float4 col */      \
            ra[i] = *(const float4*)(A + (size_t)(bm + ar) * 256 + (c) * 32 + ac * 4); \
        }                                                                      \
    } while (0)

#define STA(s)                                                                 \
    do {                                                                       \
        _Pragma("unroll")                                                      \
        for (int i = 0; i < 4; ++i) {                                          \
            int idx = tid + i * 128;                                           \
            int ar = idx >> 3, ac = idx & 7;                                   \
            int mt = ar >> 4, r = ar & 15;                                     \
            int gl = r & 7, hi = r >> 3;                                       \
            int kk16 = ac >> 2;                                                \
            int half = (ac & 3) >> 1;                                          \
            int t4v0 = (ac & 1) * 2;                                           \
            int base = ((kk16 * 4 + mt) * 32 + gl * 4 + t4v0) * 4 + half * 2 + hi; \
            sA[s][base]     = packh2(ra[i].x, ra[i].y);                        \
            sA[s][base + 4] = packh2(ra[i].z, ra[i].w);                        \
        }                                                                      \
    } while (0)

#define LDB_ASYNC(c, s)                                                        \
    do {                                                                       \
        uint32_t base = smem_u32(sB[s]);                                       \
        const uint32_t* src = g_BfragH + (size_t)(c) * 4096;                   \
        _Pragma("unroll")                                                      \
        for (int i = 0; i < 8; ++i) {                                          \
            int off = (tid + i * 128) * 4;                                     \
            cp_async16(base + off * 4, src + off);                             \
        }                                                                      \
        cp_commit();                                                           \
    } while (0)

    LDA(0);
    LDB_ASYNC(0, 0);
    STA(0);
    cp_wait0();
    __syncthreads();

#pragma unroll 1
    for (int c = 0; c < 8; ++c) {
        const int st = c & 1;
        const bool more = (c < 7);
        if (more) { LDA(c + 1); LDB_ASYNC(c + 1, st ^ 1); }

        uint32_t* sBc = sB[st];
#pragma unroll
        for (int kk16 = 0; kk16 < 2; ++kk16) {
            uint4 af[4];
#pragma unroll
            for (int i = 0; i < 4; ++i)
                af[i] = *(uint4*)&sA[st][((kk16 * 4 + i) * 32 + lane) * 4];
            uint2 bf[8];
#pragma unroll
            for (int j = 0; j < 8; ++j)
                bf[j] = *(uint2*)&sBc[((kk16 * 256 + no + 8 * j + g) * 4 + t4) * 2];
#pragma unroll
            for (int i = 0; i < 4; ++i)
#pragma unroll
                for (int j = 0; j < 8; ++j)
                    mma_f16(acc[i][j], af[i].x, af[i].y, af[i].z, af[i].w,
                            bf[j].x, bf[j].y);
        }

        if (more) STA(st ^ 1);
        cp_wait0();
        __syncthreads();
    }

    // epilogue with bias -> fp16
#pragma unroll
    for (int j = 0; j < 8; ++j) {
        int gn = no + 8 * j + 2 * t4;
        float2 bv = *(const float2*)(bias + gn);
#pragma unroll
        for (int i = 0; i < 4; ++i) {
            int gm = bm + i * 16 + g;
            *(__half2*)(C + (size_t)gm * 256 + gn) =
                __floats2half2_rn(acc[i][j][0] + bv.x, acc[i][j][1] + bv.y);
            *(__half2*)(C + (size_t)(gm + 8) * 256 + gn) =
                __floats2half2_rn(acc[i][j][2] + bv.x, acc[i][j][3] + bv.y);
        }
    }
#undef LDA
#undef STA
#undef LDB_ASYNC
}

// ---------------------------------------------------------------------------
// Small-GEMM kernel (exact fp32), 64x64 tiles, per-thread 4x4, 256 threads.
// Column-concatenated weights: cols [0,N1) from W1/b1, cols [N1,N) from W2/b2.
// ---------------------------------------------------------------------------
__global__ __launch_bounds__(256, 4)
void gemm64_kernel(const float* __restrict__ A,
                   const float* __restrict__ W1, const float* __restrict__ b1,
                   const float* __restrict__ W2, const float* __restrict__ b2,
                   int N1, int N2,
                   float* __restrict__ C,
                   int N, int K, int ldc)
{
    __shared__ float As[16][68];
    __shared__ float Bs[16][68];

    const int bm  = blockIdx.y * 64;
    const int bn  = blockIdx.x * 64;
    const int tid = threadIdx.x;
    const int tx  = tid & 15;
    const int ty  = tid >> 4;

    float acc[4][4];
#pragma unroll
    for (int i = 0; i < 4; ++i)
#pragma unroll
        for (int j = 0; j < 4; ++j) acc[i][j] = 0.f;

    const int a_row = tid >> 2;
    const int a_col = (tid & 3) << 2;
    const int b_row = tid >> 4;
    const int b_col = (tid & 15) << 2;

    for (int k0 = 0; k0 < K; k0 += 16) {
        {
            float4 v = *(const float4*)(A + (size_t)(bm + a_row) * K + k0 + a_col);
            As[a_col + 0][a_row] = v.x;
            As[a_col + 1][a_row] = v.y;
            As[a_col + 2][a_row] = v.z;
            As[a_col + 3][a_row] = v.w;
        }
        {
            int gk = k0 + b_row;
            float v[4];
#pragma unroll
            for (int e = 0; e < 4; ++e) {
                int gn = bn + b_col + e;
                float x = 0.f;
                if (gn < N1)       x = W1[(size_t)gk * N1 + gn];
                else if (gn < N)   x = W2[(size_t)gk * N2 + gn - N1];
                v[e] = x;
            }
            *(float4*)&Bs[b_row][b_col] = make_float4(v[0], v[1], v[2], v[3]);
        }
        __syncthreads();

#pragma unroll
        for (int k = 0; k < 16; ++k) {
            float4 a4 = *(const float4*)&As[k][ty * 4];
            float4 b4 = *(const float4*)&Bs[k][tx * 4];
            float ar2[4] = {a4.x, a4.y, a4.z, a4.w};
            float br2[4] = {b4.x, b4.y, b4.z, b4.w};
#pragma unroll
            for (int i = 0; i < 4; ++i)
#pragma unroll
                for (int j = 0; j < 4; ++j)
                    acc[i][j] += ar2[i] * br2[j];
        }
        __syncthreads();
    }

    float bv[4];
#pragma unroll
    for (int j = 0; j < 4; ++j) {
        int gn = bn + tx * 4 + j;
        bv[j] = (gn < N1) ? b1[gn] : ((gn < N) ? b2[gn - N1] : 0.f);
    }
#pragma unroll
    for (int i = 0; i < 4; ++i) {
        int gm = bm + ty * 4 + i;
#pragma unroll
        for (int j = 0; j < 4; ++j) {
            int gn = bn + tx * 4 + j;
            if (gn < N) C[(size_t)gm * ldc + gn] = acc[i][j] + bv[j];
        }
    }
}

// ---------------------------------------------------------------------------
// Deformable sampling + softmax, two-phase (round-9 winner).
// ---------------------------------------------------------------------------
__global__ __launch_bounds__(256)
void sample_kernel(const float* __restrict__ ref,
                   float* __restrict__ out)
{
    __shared__ float4 s_w[8][N_LP];
    __shared__ int4   s_o[8][N_LP];

    const int row  = blockIdx.x;
    const int b    = row / LEN_Q;
    const int h    = threadIdx.x >> 5;
    const int lane = threadIdx.x & 31;

    const float* prm  = g_params + row * P_LD;
    const float* attp = prm + 192 + h * N_LP;

    float lgt = (lane < N_LP) ? attp[lane] : -3.0e38f;
    float mx = lgt;
#pragma unroll
    for (int s = 16; s; s >>= 1) mx = fmaxf(mx, __shfl_xor_sync(0xffffffffu, mx, s));
    float e = (lane < N_LP) ? __expf(lgt - mx) : 0.f;
    float sum = e;
#pragma unroll
    for (int s = 16; s; s >>= 1) sum += __shfl_xor_sync(0xffffffffu, sum, s);
    float aw = e / sum;

    if (lane < N_LP) {
        const int   lvl_start[3] = {0, 6400, 8000};
        const int   lvl_W[3]     = {80, 40, 20};
        const float lvl_inv[3]   = {1.f / 80.f, 1.f / 40.f, 1.f / 20.f};
        const int l  = lane >> 2;
        const int Wl = lvl_W[l];
        const int st = lvl_start[l];

        float2 off2 = ((const float2*)(prm + h * (N_LP * 2)))[lane];
        const float* rp = ref + row * (N_LEVELS * 2);
        float lx = fmaf(off2.x, lvl_inv[l], rp[2 * l + 0]);
        float ly = fmaf(off2.y, lvl_inv[l], rp[2 * l + 1]);

        float ix = fmaf(lx, (float)Wl, -0.5f);
        float iy = fmaf(ly, (float)Wl, -0.5f);
        float fix = floorf(ix), fiy = floorf(iy);
        int   x0 = (int)fix,   y0 = (int)fiy;
        float fx = ix - fix,   fy = iy - fiy;
        int   x1 = x0 + 1,     y1 = y0 + 1;

        bool vx0 = (x0 >= 0) & (x0 < Wl);
        bool vx1 = (x1 >= 0) & (x1 < Wl);
        bool vy0 = (y0 >= 0) & (y0 < Wl);
        bool vy1 = (y1 >= 0) & (y1 < Wl);

        int cx0 = min(max(x0, 0), Wl - 1), cx1 = min(max(x1, 0), Wl - 1);
        int cy0 = min(max(y0, 0), Wl - 1), cy1 = min(max(y1, 0), Wl - 1);

        float gx0 = 1.f - fx, gy0 = 1.f - fy;
        float w00 = (vy0 & vx0) ? aw * gy0 * gx0 : 0.f;
        float w01 = (vy0 & vx1) ? aw * gy0 * fx  : 0.f;
        float w10 = (vy1 & vx0) ? aw * fy  * gx0 : 0.f;
        float w11 = (vy1 & vx1) ? aw * fy  * fx  : 0.f;

        int r0 = st + cy0 * Wl, r1 = st + cy1 * Wl;
        s_w[h][lane] = make_float4(w00, w01, w10, w11);
        s_o[h][lane] = make_int4(r0 + cx0, r0 + cx1, r1 + cx0, r1 + cx1);
    }
    __syncwarp();

    const __half* vb = g_valueH + ((unsigned)b * (N_TOTAL * D_MODEL)
                                   + (unsigned)h * HEAD_DIM + (unsigned)lane);
    float acc = 0.f;
#pragma unroll
    for (int j = 0; j < N_LP; ++j) {
        float4 w = s_w[h][j];
        int4   o = s_o[h][j];
        acc = fmaf(w.x, __half2float(vb[(unsigned)o.x << 8]), acc);
        acc = fmaf(w.y, __half2float(vb[(unsigned)o.y << 8]), acc);
        acc = fmaf(w.z, __half2float(vb[(unsigned)o.z << 8]), acc);
        acc = fmaf(w.w, __half2float(vb[(unsigned)o.w << 8]), acc);
    }

    out[row * D_MODEL + h * HEAD_DIM + lane] = acc;
}

// ---------------------------------------------------------------------------
extern "C" void kernel_launch(void* const* d_in, const int* in_sizes, int n_in,
                              void* d_out, int out_size)
{
    const float* query  = (const float*)d_in[0];
    const float* refpts = (const float*)d_in[1];
    const float* inputf = (const float*)d_in[2];
    const float* W_off  = (const float*)d_in[3];
    const float* b_off  = (const float*)d_in[4];
    const float* W_attn = (const float*)d_in[5];
    const float* b_attn = (const float*)d_in[6];
    const float* W_val  = (const float*)d_in[7];
    const float* b_val  = (const float*)d_in[8];
    const float* W_out  = (const float*)d_in[9];
    const float* b_out  = (const float*)d_in[10];
    float* outp = (float*)d_out;

    __half* valueH; cudaGetSymbolAddress((void**)&valueH, g_valueH);
    float* params;  cudaGetSymbolAddress((void**)&params,  g_params);
    float* sampled; cudaGetSymbolAddress((void**)&sampled, g_sampled);

    cudaFuncSetAttribute(gemm1_mma_kernel,
                         cudaFuncAttributeMaxDynamicSharedMemorySize, GEMM1_DYN);

    // 0. W_val -> fp16 fragment-order buffer
    prep_w_kernel<<<128, 256>>>(W_val);

    // 1. value projection (mma.sync fp16) -> fp16 value; 2 CTAs/SM
    gemm1_mma_kernel<<<M1 / 64, 128, GEMM1_DYN>>>(inputf, b_val, valueH);

    // 2. fused offsets+attn: (4800,256)@(256,288)+b -> params (fp32)
    {
        dim3 grid((P_LD + 63) / 64, NQ / 64);
        gemm64_kernel<<<grid, 256>>>(query, W_off, b_off, W_attn, b_attn,
                                     192, 96, params, P_LD, D_MODEL, P_LD);
    }
    // 3. softmax + deformable bilinear sampling
    sample_kernel<<<NQ, 256>>>(refpts, sampled);

    // 4. output projection: (4800,256)@(256,256)+b -> d_out (fp32)
    {
        dim3 grid(256 / 64, NQ / 64);
        gemm64_kernel<<<grid, 256>>>(sampled, W_out, b_out, W_out, b_out,
                                     256, 256, outp, 256, D_MODEL, 256);
    }
    (void)in_sizes; (void)n_in; (void)out_size;
}

// round 17
// speedup vs baseline: 1.2194x; 1.0098x over previous
#include <cuda_runtime.h>
#include <cuda_fp16.h>
#include <math.h>
#include <stdint.h>

#define D_MODEL   256
#define N_HEADS   8
#define HEAD_DIM  32
#define N_LEVELS  3
#define N_POINTS  4
#define N_LP      12
#define B_SZ      16
#define LEN_Q     300
#define N_TOTAL   8400
#define NQ        (B_SZ * LEN_Q)      // 4800
#define P_LD      288
#define M1        (B_SZ * N_TOTAL)    // 134400

// Scratch (allocation-free rule: __device__ globals)
__device__ __half   g_valueH [(size_t)M1 * D_MODEL];   // fp16 value
__device__ float    g_params [(size_t)NQ * P_LD];
__device__ float    g_sampled[(size_t)NQ * D_MODEL];
__device__ uint32_t g_BfragH [32768];     // W_val fragment order (N=256)

// ---------------------------------------------------------------------------
__device__ __forceinline__ uint32_t packh2(float lo, float hi) {
    __half2 h = __floats2half2_rn(lo, hi);
    return *(uint32_t*)&h;
}
__device__ __forceinline__ uint32_t smem_u32(const void* p) {
    uint32_t a;
    asm("{ .reg .u64 t; cvta.to.shared.u64 t, %1; cvt.u32.u64 %0, t; }"
        : "=r"(a) : "l"(p));
    return a;
}
__device__ __forceinline__ void cp_async16(uint32_t dst, const void* src) {
    asm volatile("cp.async.cg.shared.global [%0], [%1], 16;"
                 :: "r"(dst), "l"(src) : "memory");
}
__device__ __forceinline__ void cp_commit() {
    asm volatile("cp.async.commit_group;" ::: "memory");
}
__device__ __forceinline__ void cp_wait0() {
    asm volatile("cp.async.wait_group 0;" ::: "memory");
}
__device__ __forceinline__ void mma_f16(float c[4], uint32_t a0, uint32_t a1,
                                        uint32_t a2, uint32_t a3,
                                        uint32_t b0, uint32_t b1) {
    asm volatile(
        "mma.sync.aligned.m16n8k16.row.col.f32.f16.f16.f32 "
        "{%0,%1,%2,%3}, {%4,%5,%6,%7}, {%8,%9}, {%0,%1,%2,%3};"
        : "+f"(c[0]), "+f"(c[1]), "+f"(c[2]), "+f"(c[3])
        : "r"(a0), "r"(a1), "r"(a2), "r"(a3), "r"(b0), "r"(b1));
}

// ---------------------------------------------------------------------------
// W_val[k][n] -> fp16x2 B-fragment order.
// ---------------------------------------------------------------------------
__global__ void prep_w_kernel(const float* __restrict__ W) {
    int id = blockIdx.x * 256 + threadIdx.x;   // 0..32767
    int kc = id >> 12, ci = id & 4095;
    int half = ci & 1, t4v = (ci >> 1) & 3, n = (ci >> 3) & 255, kk16 = ci >> 11;
    int k0 = kc * 32 + kk16 * 16 + half * 8 + t4v * 2;
    g_BfragH[id] = packh2(W[(size_t)k0 * 256 + n], W[(size_t)(k0 + 1) * 256 + n]);
}

// ---------------------------------------------------------------------------
// GEMM1: value[M1,256] = A[M1,256] @ W_val + bias -> fp16
// CTA 64x256, 128 threads (4 warps), warp tile 64x64, BK=32 double-buffered.
// 2 CTAs/SM. (At the legacy-HMMA issue-rate wall; structure frozen.)
// ---------------------------------------------------------------------------
#define GEMM1_DYN (40 * 1024)

__global__ __launch_bounds__(128, 2)
void gemm1_mma_kernel(const float* __restrict__ A,
                      const float* __restrict__ bias,
                      __half* __restrict__ C)
{
    extern __shared__ uint32_t smw[];
    uint32_t* sA[2] = { smw,        smw + 1024 };
    uint32_t* sB[2] = { smw + 2048, smw + 6144 };

    const int tid  = threadIdx.x;
    const int warp = tid >> 5;
    const int lane = tid & 31;
    const int g    = lane >> 2;
    const int t4   = lane & 3;
    const int no   = warp * 64;
    const int bm   = blockIdx.x * 64;

    float acc[4][8][4];
#pragma unroll
    for (int i = 0; i < 4; ++i)
#pragma unroll
        for (int j = 0; j < 8; ++j)
#pragma unroll
            for (int r = 0; r < 4; ++r) acc[i][j][r] = 0.f;

    float4 ra[4];

#define LDA(c)                                                                 \
    do {                                                                       \
        _Pragma("unroll")                                                      \
        for (int i = 0; i < 4; ++i) {                                          \
            int idx = tid + i * 128;                                           \
            int ar = idx >> 3, ac = idx & 7;                                   \
            ra[i] = *(const float4*)(A + (size_t)(bm + ar) * 256 + (c) * 32 + ac * 4); \
        }                                                                      \
    } while (0)

#define STA(s)                                                                 \
    do {                                                                       \
        _Pragma("unroll")                                                      \
        for (int i = 0; i < 4; ++i) {                                          \
            int idx = tid + i * 128;                                           \
            int ar = idx >> 3, ac = idx & 7;                                   \
            int mt = ar >> 4, r = ar & 15;                                     \
            int gl = r & 7, hi = r >> 3;                                       \
            int kk16 = ac >> 2;                                                \
            int half = (ac & 3) >> 1;                                          \
            int t4v0 = (ac & 1) * 2;                                           \
            int base = ((kk16 * 4 + mt) * 32 + gl * 4 + t4v0) * 4 + half * 2 + hi; \
            sA[s][base]     = packh2(ra[i].x, ra[i].y);                        \
            sA[s][base + 4] = packh2(ra[i].z, ra[i].w);                        \
        }                                                                      \
    } while (0)

#define LDB_ASYNC(c, s)                                                        \
    do {                                                                       \
        uint32_t base = smem_u32(sB[s]);                                       \
        const uint32_t* src = g_BfragH + (size_t)(c) * 4096;                   \
        _Pragma("unroll")                                                      \
        for (int i = 0; i < 8; ++i) {                                          \
            int off = (tid + i * 128) * 4;                                     \
            cp_async16(base + off * 4, src + off);                             \
        }                                                                      \
        cp_commit();                                                           \
    } while (0)

    LDA(0);
    LDB_ASYNC(0, 0);
    STA(0);
    cp_wait0();
    __syncthreads();

#pragma unroll 1
    for (int c = 0; c < 8; ++c) {
        const int st = c & 1;
        const bool more = (c < 7);
        if (more) { LDA(c + 1); LDB_ASYNC(c + 1, st ^ 1); }

        uint32_t* sBc = sB[st];
#pragma unroll
        for (int kk16 = 0; kk16 < 2; ++kk16) {
            uint4 af[4];
#pragma unroll
            for (int i = 0; i < 4; ++i)
                af[i] = *(uint4*)&sA[st][((kk16 * 4 + i) * 32 + lane) * 4];
            uint2 bf[8];
#pragma unroll
            for (int j = 0; j < 8; ++j)
                bf[j] = *(uint2*)&sBc[((kk16 * 256 + no + 8 * j + g) * 4 + t4) * 2];
#pragma unroll
            for (int i = 0; i < 4; ++i)
#pragma unroll
                for (int j = 0; j < 8; ++j)
                    mma_f16(acc[i][j], af[i].x, af[i].y, af[i].z, af[i].w,
                            bf[j].x, bf[j].y);
        }

        if (more) STA(st ^ 1);
        cp_wait0();
        __syncthreads();
    }

    // epilogue with bias -> fp16
#pragma unroll
    for (int j = 0; j < 8; ++j) {
        int gn = no + 8 * j + 2 * t4;
        float2 bv = *(const float2*)(bias + gn);
#pragma unroll
        for (int i = 0; i < 4; ++i) {
            int gm = bm + i * 16 + g;
            *(__half2*)(C + (size_t)gm * 256 + gn) =
                __floats2half2_rn(acc[i][j][0] + bv.x, acc[i][j][1] + bv.y);
            *(__half2*)(C + (size_t)(gm + 8) * 256 + gn) =
                __floats2half2_rn(acc[i][j][2] + bv.x, acc[i][j][3] + bv.y);
        }
    }
#undef LDA
#undef STA
#undef LDB_ASYNC
}

// ---------------------------------------------------------------------------
// Small-GEMM kernel (exact fp32), 64x64 tiles, per-thread 4x4, 256 threads.
// Column-concatenated weights: cols [0,N1) from W1/b1, cols [N1,N) from W2/b2.
// ---------------------------------------------------------------------------
__global__ __launch_bounds__(256, 4)
void gemm64_kernel(const float* __restrict__ A,
                   const float* __restrict__ W1, const float* __restrict__ b1,
                   const float* __restrict__ W2, const float* __restrict__ b2,
                   int N1, int N2,
                   float* __restrict__ C,
                   int N, int K, int ldc)
{
    __shared__ float As[16][68];
    __shared__ float Bs[16][68];

    const int bm  = blockIdx.y * 64;
    const int bn  = blockIdx.x * 64;
    const int tid = threadIdx.x;
    const int tx  = tid & 15;
    const int ty  = tid >> 4;

    float acc[4][4];
#pragma unroll
    for (int i = 0; i < 4; ++i)
#pragma unroll
        for (int j = 0; j < 4; ++j) acc[i][j] = 0.f;

    const int a_row = tid >> 2;
    const int a_col = (tid & 3) << 2;
    const int b_row = tid >> 4;
    const int b_col = (tid & 15) << 2;

    for (int k0 = 0; k0 < K; k0 += 16) {
        {
            float4 v = *(const float4*)(A + (size_t)(bm + a_row) * K + k0 + a_col);
            As[a_col + 0][a_row] = v.x;
            As[a_col + 1][a_row] = v.y;
            As[a_col + 2][a_row] = v.z;
            As[a_col + 3][a_row] = v.w;
        }
        {
            int gk = k0 + b_row;
            float v[4];
#pragma unroll
            for (int e = 0; e < 4; ++e) {
                int gn = bn + b_col + e;
                float x = 0.f;
                if (gn < N1)       x = W1[(size_t)gk * N1 + gn];
                else if (gn < N)   x = W2[(size_t)gk * N2 + gn - N1];
                v[e] = x;
            }
            *(float4*)&Bs[b_row][b_col] = make_float4(v[0], v[1], v[2], v[3]);
        }
        __syncthreads();

#pragma unroll
        for (int k = 0; k < 16; ++k) {
            float4 a4 = *(const float4*)&As[k][ty * 4];
            float4 b4 = *(const float4*)&Bs[k][tx * 4];
            float ar2[4] = {a4.x, a4.y, a4.z, a4.w};
            float br2[4] = {b4.x, b4.y, b4.z, b4.w};
#pragma unroll
            for (int i = 0; i < 4; ++i)
#pragma unroll
                for (int j = 0; j < 4; ++j)
                    acc[i][j] += ar2[i] * br2[j];
        }
        __syncthreads();
    }

    float bv[4];
#pragma unroll
    for (int j = 0; j < 4; ++j) {
        int gn = bn + tx * 4 + j;
        bv[j] = (gn < N1) ? b1[gn] : ((gn < N) ? b2[gn - N1] : 0.f);
    }
#pragma unroll
    for (int i = 0; i < 4; ++i) {
        int gm = bm + ty * 4 + i;
#pragma unroll
        for (int j = 0; j < 4; ++j) {
            int gn = bn + tx * 4 + j;
            if (gn < N) C[(size_t)gm * ldc + gn] = acc[i][j] + bv[j];
        }
    }
}

// ---------------------------------------------------------------------------
// Deformable sampling + softmax, two-phase; phase 2 uses 4 corner-wise
// accumulators to cut the serial FMA dependency chain 4x.
// ---------------------------------------------------------------------------
__global__ __launch_bounds__(256)
void sample_kernel(const float* __restrict__ ref,
                   float* __restrict__ out)
{
    __shared__ float4 s_w[8][N_LP];
    __shared__ int4   s_o[8][N_LP];

    const int row  = blockIdx.x;
    const int b    = row / LEN_Q;
    const int h    = threadIdx.x >> 5;
    const int lane = threadIdx.x & 31;

    const float* prm  = g_params + row * P_LD;
    const float* attp = prm + 192 + h * N_LP;

    float lgt = (lane < N_LP) ? attp[lane] : -3.0e38f;
    float mx = lgt;
#pragma unroll
    for (int s = 16; s; s >>= 1) mx = fmaxf(mx, __shfl_xor_sync(0xffffffffu, mx, s));
    float e = (lane < N_LP) ? __expf(lgt - mx) : 0.f;
    float sum = e;
#pragma unroll
    for (int s = 16; s; s >>= 1) sum += __shfl_xor_sync(0xffffffffu, sum, s);
    float aw = e / sum;

    if (lane < N_LP) {
        const int   lvl_start[3] = {0, 6400, 8000};
        const int   lvl_W[3]     = {80, 40, 20};
        const float lvl_inv[3]   = {1.f / 80.f, 1.f / 40.f, 1.f / 20.f};
        const int l  = lane >> 2;
        const int Wl = lvl_W[l];
        const int st = lvl_start[l];

        float2 off2 = ((const float2*)(prm + h * (N_LP * 2)))[lane];
        const float* rp = ref + row * (N_LEVELS * 2);
        float lx = fmaf(off2.x, lvl_inv[l], rp[2 * l + 0]);
        float ly = fmaf(off2.y, lvl_inv[l], rp[2 * l + 1]);

        float ix = fmaf(lx, (float)Wl, -0.5f);
        float iy = fmaf(ly, (float)Wl, -0.5f);
        float fix = floorf(ix), fiy = floorf(iy);
        int   x0 = (int)fix,   y0 = (int)fiy;
        float fx = ix - fix,   fy = iy - fiy;
        int   x1 = x0 + 1,     y1 = y0 + 1;

        bool vx0 = (x0 >= 0) & (x0 < Wl);
        bool vx1 = (x1 >= 0) & (x1 < Wl);
        bool vy0 = (y0 >= 0) & (y0 < Wl);
        bool vy1 = (y1 >= 0) & (y1 < Wl);

        int cx0 = min(max(x0, 0), Wl - 1), cx1 = min(max(x1, 0), Wl - 1);
        int cy0 = min(max(y0, 0), Wl - 1), cy1 = min(max(y1, 0), Wl - 1);

        float gx0 = 1.f - fx, gy0 = 1.f - fy;
        float w00 = (vy0 & vx0) ? aw * gy0 * gx0 : 0.f;
        float w01 = (vy0 & vx1) ? aw * gy0 * fx  : 0.f;
        float w10 = (vy1 & vx0) ? aw * fy  * gx0 : 0.f;
        float w11 = (vy1 & vx1) ? aw * fy  * fx  : 0.f;

        int r0 = st + cy0 * Wl, r1 = st + cy1 * Wl;
        s_w[h][lane] = make_float4(w00, w01, w10, w11);
        s_o[h][lane] = make_int4(r0 + cx0, r0 + cx1, r1 + cx0, r1 + cx1);
    }
    __syncwarp();

    const __half* vb = g_valueH + ((unsigned)b * (N_TOTAL * D_MODEL)
                                   + (unsigned)h * HEAD_DIM + (unsigned)lane);
    float a0 = 0.f, a1 = 0.f, a2 = 0.f, a3 = 0.f;
#pragma unroll
    for (int j = 0; j < N_LP; ++j) {
        float4 w = s_w[h][j];
        int4   o = s_o[h][j];
        a0 = fmaf(w.x, __half2float(vb[(unsigned)o.x << 8]), a0);
        a1 = fmaf(w.y, __half2float(vb[(unsigned)o.y << 8]), a1);
        a2 = fmaf(w.z, __half2float(vb[(unsigned)o.z << 8]), a2);
        a3 = fmaf(w.w, __half2float(vb[(unsigned)o.w << 8]), a3);
    }

    out[row * D_MODEL + h * HEAD_DIM + lane] = (a0 + a1) + (a2 + a3);
}

// ---------------------------------------------------------------------------
extern "C" void kernel_launch(void* const* d_in, const int* in_sizes, int n_in,
                              void* d_out, int out_size)
{
    const float* query  = (const float*)d_in[0];
    const float* refpts = (const float*)d_in[1];
    const float* inputf = (const float*)d_in[2];
    const float* W_off  = (const float*)d_in[3];
    const float* b_off  = (const float*)d_in[4];
    const float* W_attn = (const float*)d_in[5];
    const float* b_attn = (const float*)d_in[6];
    const float* W_val  = (const float*)d_in[7];
    const float* b_val  = (const float*)d_in[8];
    const float* W_out  = (const float*)d_in[9];
    const float* b_out  = (const float*)d_in[10];
    float* outp = (float*)d_out;

    __half* valueH; cudaGetSymbolAddress((void**)&valueH, g_valueH);
    float* params;  cudaGetSymbolAddress((void**)&params,  g_params);
    float* sampled; cudaGetSymbolAddress((void**)&sampled, g_sampled);

    cudaFuncSetAttribute(gemm1_mma_kernel,
                         cudaFuncAttributeMaxDynamicSharedMemorySize, GEMM1_DYN);

    // 0. W_val -> fp16 fragment-order buffer
    prep_w_kernel<<<128, 256>>>(W_val);

    // 1. value projection (mma.sync fp16) -> fp16 value; 2 CTAs/SM
    gemm1_mma_kernel<<<M1 / 64, 128, GEMM1_DYN>>>(inputf, b_val, valueH);

    // 2. fused offsets+attn: (4800,256)@(256,288)+b -> params (fp32)
    {
        dim3 grid((P_LD + 63) / 64, NQ / 64);
        gemm64_kernel<<<grid, 256>>>(query, W_off, b_off, W_attn, b_attn,
                                     192, 96, params, P_LD, D_MODEL, P_LD);
    }
    // 3. softmax + deformable bilinear sampling
    sample_kernel<<<NQ, 256>>>(refpts, sampled);

    // 4. output projection: (4800,256)@(256,256)+b -> d_out (fp32)
    {
        dim3 grid(256 / 64, NQ / 64);
        gemm64_kernel<<<grid, 256>>>(sampled, W_out, b_out, W_out, b_out,
                                     256, 256, outp, 256, D_MODEL, 256);
    }
    (void)in_sizes; (void)n_in; (void)out_size;
}